// round 10
// baseline (speedup 1.0000x reference)
#include <cuda_runtime.h>
#include <cuda_bf16.h>
#include <cstdint>

#define M_TOK   16384
#define D_DIM   1024
#define H_DIM   4096

// ---------------- scratch (static device memory; no allocations) -----------
__device__ __align__(16) __nv_bfloat16 g_xb [M_TOK * D_DIM];
__device__ __align__(16) __nv_bfloat16 g_w1b[H_DIM * D_DIM];
__device__ __align__(16) __nv_bfloat16 g_w2b[D_DIM * H_DIM];
__device__ __align__(16) float         g_h  [(size_t)M_TOK * H_DIM];
__device__ __align__(16) __nv_bfloat16 g_hb [(size_t)M_TOK * H_DIM];
__device__ unsigned g_amax[4];      // 0: x, 1: w1, 2: w2, 3: h (fp32 bits)

// ---------------- helpers ---------------------------------------------------
__device__ __forceinline__ unsigned smem_u32(const void* p) {
    return (unsigned)__cvta_generic_to_shared(p);
}
__device__ __forceinline__ void cp16(unsigned dst, const void* src) {
    asm volatile("cp.async.cg.shared.global [%0], [%1], 16;\n" :: "r"(dst), "l"(src));
}
__device__ __forceinline__ void ldsm4(unsigned& r0, unsigned& r1, unsigned& r2,
                                      unsigned& r3, unsigned addr) {
    asm volatile("ldmatrix.sync.aligned.m8n8.x4.shared.b16 {%0,%1,%2,%3}, [%4];"
                 : "=r"(r0), "=r"(r1), "=r"(r2), "=r"(r3) : "r"(addr));
}

#define MMA_BF16(d, a, b)                                                      \
    asm volatile(                                                              \
        "mma.sync.aligned.m16n8k16.row.col.f32.bf16.bf16.f32 "                 \
        "{%0,%1,%2,%3},{%4,%5,%6,%7},{%8,%9},{%0,%1,%2,%3};"                   \
        : "+f"(d[0]), "+f"(d[1]), "+f"(d[2]), "+f"(d[3])                       \
        : "r"(a[0]), "r"(a[1]), "r"(a[2]), "r"(a[3]), "r"(b[0]), "r"(b[1]))

#define MBARRIER_INIT(addr, cnt) \
    asm volatile("mbarrier.init.shared.b64 [%0], %1;" :: "r"(addr), "r"(cnt) : "memory")
#define MBARRIER_INVAL(addr) \
    asm volatile("mbarrier.inval.shared.b64 [%0];" :: "r"(addr) : "memory")
#define MBARRIER_ARRIVE(addr) \
    asm volatile("mbarrier.arrive.shared.b64 _, [%0];" :: "r"(addr) : "memory")

#define MBARRIER_WAIT_PARITY(mbar_smem_addr, phase_parity) do {               \
    uint32_t _mbar = (uint32_t)(mbar_smem_addr);                              \
    uint32_t _parity = (uint32_t)(phase_parity);                              \
    uint32_t _done;                                                           \
    asm volatile(                                                             \
        "{\n\t.reg .pred p;\n\t"                                              \
        "mbarrier.try_wait.parity.acquire.cta.shared::cta.b64 p, [%1], %2;\n\t" \
        "selp.b32 %0, 1, 0, p;\n\t}"                                          \
        : "=r"(_done) : "r"(_mbar), "r"(_parity) : "memory");                 \
    if (!_done) {                                                             \
        asm volatile(                                                         \
            "{\n\t.reg .pred P1;\n\t"                                         \
            "WAIT_LOOP_%=:\n\t"                                               \
            "mbarrier.try_wait.parity.acquire.cta.shared::cta.b64 P1, [%0], %1, 0x989680;\n\t" \
            "@P1 bra.uni WAIT_DONE_%=;\n\t"                                   \
            "bra.uni WAIT_LOOP_%=;\n\t"                                       \
            "WAIT_DONE_%=:\n\t}"                                              \
            :: "r"(_mbar), "r"(_parity) : "memory");                          \
    }                                                                         \
} while (0)

// ---------------- fused prep kernels ----------------------------------------
__global__ void init_kernel() {
    if (threadIdx.x < 4) g_amax[threadIdx.x] = 0u;
}

// blocks [0,1024): x | [1024,1280): w1 | [1280,1536): w2
__global__ void absmax_all_kernel(const float4* __restrict__ x,
                                  const float4* __restrict__ w1,
                                  const float4* __restrict__ w2) {
    const float4* p;
    int n4, slot, lb, nb;
    int b = blockIdx.x;
    if (b < 1024)      { p = x;  n4 = (M_TOK * D_DIM) / 4; slot = 0; lb = b;        nb = 1024; }
    else if (b < 1280) { p = w1; n4 = (H_DIM * D_DIM) / 4; slot = 1; lb = b - 1024; nb = 256; }
    else               { p = w2; n4 = (D_DIM * H_DIM) / 4; slot = 2; lb = b - 1280; nb = 256; }

    float m = 0.f;
    for (int i = lb * blockDim.x + threadIdx.x; i < n4; i += nb * blockDim.x) {
        float4 v = p[i];
        m = fmaxf(m, fmaxf(fmaxf(fabsf(v.x), fabsf(v.y)),
                           fmaxf(fabsf(v.z), fabsf(v.w))));
    }
    #pragma unroll
    for (int o = 16; o > 0; o >>= 1)
        m = fmaxf(m, __shfl_xor_sync(0xffffffffu, m, o));
    __shared__ float sm[8];
    if ((threadIdx.x & 31) == 0) sm[threadIdx.x >> 5] = m;
    __syncthreads();
    if (threadIdx.x == 0) {
        float v = sm[0];
        #pragma unroll
        for (int i = 1; i < 8; ++i) v = fmaxf(v, sm[i]);
        atomicMax(&g_amax[slot], __float_as_uint(v));
    }
}

__device__ __forceinline__ float quantf(float v, float scale) {
    return fminf(fmaxf(rintf(v / scale), -127.f), 127.f);
}
__device__ __forceinline__ unsigned short bf16bits(float v) {
    __nv_bfloat16 h = __float2bfloat16(v);
    return *(unsigned short*)&h;
}

// blocks [0,16384): x | [16384,20480): w1 | [20480,24576): w2  (all -> bf16 ints)
__global__ void quant_all_kernel(const float4* __restrict__ x,
                                 const float4* __restrict__ w1,
                                 const float4* __restrict__ w2) {
    int b = blockIdx.x;
    const float4* src;
    ushort4* dst;
    int i, slot;
    if (b < 16384)      { src = x;  dst = (ushort4*)g_xb;  i = b * blockDim.x + threadIdx.x;            slot = 0; }
    else if (b < 20480) { src = w1; dst = (ushort4*)g_w1b; i = (b - 16384) * blockDim.x + threadIdx.x;  slot = 1; }
    else                { src = w2; dst = (ushort4*)g_w2b; i = (b - 20480) * blockDim.x + threadIdx.x;  slot = 2; }
    float scale = fmaxf(__uint_as_float(g_amax[slot]), 1e-8f) / 127.f;
    float4 v = src[i];
    ushort4 o;
    o.x = bf16bits(quantf(v.x, scale));
    o.y = bf16bits(quantf(v.y, scale));
    o.z = bf16bits(quantf(v.z, scale));
    o.w = bf16bits(quantf(v.w, scale));
    dst[i] = o;
}

__global__ void quant_h_kernel(const float4* __restrict__ x,
                               ushort4* __restrict__ q, int n4) {
    float scale = fmaxf(__uint_as_float(g_amax[3]), 1e-8f) / 127.f;
    int i = blockIdx.x * blockDim.x + threadIdx.x;
    if (i < n4) {
        float4 v = x[i];
        ushort4 o;
        o.x = bf16bits(quantf(v.x, scale));
        o.y = bf16bits(quantf(v.y, scale));
        o.z = bf16bits(quantf(v.z, scale));
        o.w = bf16bits(quantf(v.w, scale));
        q[i] = o;
    }
}

// ---------------- warp-specialized bf16 GEMM ---------------------------------
// C[M,N] = A[M,K](bf16 row-major) * B[N,K](bf16 row-major as col-major op)
// Block tile 128x128; 160 threads: warps 0-3 consumers (64x64 each),
// warp 4 producer (all cp.async). 3-stage ring, mbarrier full/empty pairs,
// NO __syncthreads in the main loop -> consumer warps drift out of phase so
// LDSM (crossbar) overlaps MMA (tensor) across warps.
#define GSTAGE  32768
#define GB_OFF  16384
#define NSTG    3

template <int EPI>
__global__ __launch_bounds__(160, 2)
void gemm_bf16_kernel(const __nv_bfloat16* __restrict__ A,
                      const __nv_bfloat16* __restrict__ B,
                      const float* __restrict__ bias,
                      float* __restrict__ Cout,
                      int K, int N, int saslot, int sbslot) {
    extern __shared__ __align__(128) char smem[];
    __shared__ __align__(8) unsigned long long mbar[2 * NSTG];  // full[3], empty[3]
    const uint32_t sbase = smem_u32(smem);
    const uint32_t mfull  = smem_u32(&mbar[0]);
    const uint32_t mempty = smem_u32(&mbar[NSTG]);

    const int tid  = threadIdx.x;
    const int lane = tid & 31;
    const int warp = tid >> 5;

    const int row0 = blockIdx.y * 128;
    const int col0 = blockIdx.x * 128;
    const int KT = K >> 6;
    const size_t Kb = (size_t)K * 2;

    if (tid == 0) {
        #pragma unroll
        for (int s = 0; s < NSTG; ++s) {
            MBARRIER_INIT(mfull  + 8 * s, 32u);  // producer lanes via cp.async
            MBARRIER_INIT(mempty + 8 * s, 4u);   // one arrive per consumer warp
        }
    }
    __syncthreads();

    if (warp == 4) {
        // -------- producer --------
        const char* Ab = (const char*)A + (size_t)row0 * Kb;
        const char* Bb = (const char*)B + (size_t)col0 * Kb;
        for (int kt = 0; kt < KT; ++kt) {
            const int s  = kt % NSTG;
            const int ph = ((kt / NSTG) & 1) ^ 1;   // fresh barrier: parity 1 passes
            MBARRIER_WAIT_PARITY(mempty + 8 * s, ph);
            const uint32_t stoff = sbase + s * GSTAGE;
            const size_t k0b = (size_t)kt * 128;
            #pragma unroll 8
            for (int m = 0; m < 32; ++m) {
                const int idx = (m << 5) + lane;          // 0..1023
                const int row = idx >> 3;
                const int c16 = (idx & 7) << 4;
                const uint32_t sw = (uint32_t)(row * 128 + (c16 ^ ((row & 7) << 4)));
                const size_t go = (size_t)row * Kb + k0b + c16;
                cp16(stoff + sw,          Ab + go);
                cp16(stoff + GB_OFF + sw, Bb + go);
            }
            asm volatile("cp.async.mbarrier.arrive.noinc.shared::cta.b64 [%0];"
                         :: "r"(mfull + 8 * s) : "memory");
        }
    } else {
        // -------- consumers --------
        const int wm = (warp >> 1) * 64;
        const int wn = (warp & 1) * 64;

        float acc[4][8][4];
        #pragma unroll
        for (int i = 0; i < 4; ++i)
            #pragma unroll
            for (int j = 0; j < 8; ++j)
                #pragma unroll
                for (int r = 0; r < 4; ++r) acc[i][j][r] = 0.f;

        const int a_row = lane & 15;
        const int a_sel = (lane >> 4) << 4;
        const int b_row = (lane & 7) + (((lane >> 3) & 1) << 3);
        const int b_sel = (lane >> 4) << 4;
        const uint32_t a_swx = (uint32_t)((a_row & 7) << 4);
        const uint32_t b_swx = (uint32_t)((b_row & 7) << 4);
        uint32_t acol[4], bcol[4];
        #pragma unroll
        for (int ks = 0; ks < 4; ++ks) {
            acol[ks] = (uint32_t)((ks * 32 + a_sel) ^ a_swx);
            bcol[ks] = (uint32_t)((ks * 32 + b_sel) ^ b_swx);
        }
        const uint32_t aRowOff = (uint32_t)((wm + a_row) * 128);
        const uint32_t bRowOff = (uint32_t)(GB_OFF + (wn + b_row) * 128);

        for (int kt = 0; kt < KT; ++kt) {
            const int s  = kt % NSTG;
            const int ph = (kt / NSTG) & 1;
            MBARRIER_WAIT_PARITY(mfull + 8 * s, ph);

            const uint32_t st = sbase + s * GSTAGE;
            const uint32_t aBase = st + aRowOff;
            const uint32_t bBase = st + bRowOff;
            #pragma unroll
            for (int ks = 0; ks < 4; ++ks) {
                unsigned a[4][4], b[8][2];
                #pragma unroll
                for (int i = 0; i < 4; ++i)
                    ldsm4(a[i][0], a[i][1], a[i][2], a[i][3],
                          aBase + (uint32_t)(i * 16 * 128) + acol[ks]);
                #pragma unroll
                for (int jg = 0; jg < 4; ++jg)
                    ldsm4(b[2 * jg][0], b[2 * jg + 1][0],
                          b[2 * jg][1], b[2 * jg + 1][1],
                          bBase + (uint32_t)(jg * 16 * 128) + bcol[ks]);
                #pragma unroll
                for (int i = 0; i < 4; ++i)
                    #pragma unroll
                    for (int j = 0; j < 8; ++j)
                        MMA_BF16(acc[i][j], a[i], b[j]);
            }
            __syncwarp();
            if (lane == 0) MBARRIER_ARRIVE(mempty + 8 * s);
        }

        // epilogue
        const float sa = fmaxf(__uint_as_float(g_amax[saslot]), 1e-8f) / 127.f;
        const float sb = fmaxf(__uint_as_float(g_amax[sbslot]), 1e-8f) / 127.f;
        const float s  = sa * sb;

        float lmax = 0.f;
        #pragma unroll
        for (int i = 0; i < 4; ++i) {
            #pragma unroll
            for (int j = 0; j < 8; ++j) {
                const int erow0 = row0 + wm + i * 16 + (lane >> 2);
                const int ecol0 = col0 + wn + j * 8 + (lane & 3) * 2;
                #pragma unroll
                for (int rr = 0; rr < 2; ++rr) {
                    const int row = erow0 + rr * 8;
                    float t0 = fmaf(acc[i][j][rr * 2 + 0], s, bias[ecol0 + 0]);
                    float t1 = fmaf(acc[i][j][rr * 2 + 1], s, bias[ecol0 + 1]);
                    if (EPI == 0) {
                        t0 = 0.5f * t0 * (1.f + erff(t0 * 0.70710678118654752f));
                        t1 = 0.5f * t1 * (1.f + erff(t1 * 0.70710678118654752f));
                        lmax = fmaxf(lmax, fmaxf(fabsf(t0), fabsf(t1)));
                    }
                    float2 v; v.x = t0; v.y = t1;
                    *(float2*)(Cout + (size_t)row * N + ecol0) = v;
                }
            }
        }
        if (EPI == 0) {
            #pragma unroll
            for (int o = 16; o > 0; o >>= 1)
                lmax = fmaxf(lmax, __shfl_xor_sync(0xffffffffu, lmax, o));
            if (lane == 0) atomicMax(&g_amax[3], __float_as_uint(lmax));
        }
    }

    __syncthreads();
    if (tid == 0) {
        #pragma unroll
        for (int s = 0; s < 2 * NSTG; ++s) MBARRIER_INVAL(smem_u32(&mbar[s]));
    }
}

#define GEMM_SMEM (NSTG * GSTAGE)   // 98304 B

// ---------------- launch ----------------------------------------------------
extern "C" void kernel_launch(void* const* d_in, const int* in_sizes, int n_in,
                              void* d_out, int out_size) {
    const float* x  = (const float*)d_in[0];
    const float* w1 = (const float*)d_in[1];
    const float* b1 = (const float*)d_in[2];
    const float* w2 = (const float*)d_in[3];
    const float* b2 = (const float*)d_in[4];
    float* out = (float*)d_out;

    __nv_bfloat16 *xb, *w1b, *w2b, *hb;
    float* hbuf;
    cudaGetSymbolAddress((void**)&xb,   g_xb);
    cudaGetSymbolAddress((void**)&w1b,  g_w1b);
    cudaGetSymbolAddress((void**)&w2b,  g_w2b);
    cudaGetSymbolAddress((void**)&hbuf, g_h);
    cudaGetSymbolAddress((void**)&hb,   g_hb);

    cudaFuncSetAttribute(gemm_bf16_kernel<0>,
                         cudaFuncAttributeMaxDynamicSharedMemorySize, GEMM_SMEM);
    cudaFuncSetAttribute(gemm_bf16_kernel<1>,
                         cudaFuncAttributeMaxDynamicSharedMemorySize, GEMM_SMEM);

    init_kernel<<<1, 32>>>();
    absmax_all_kernel<<<1536, 256>>>((const float4*)x, (const float4*)w1,
                                     (const float4*)w2);
    quant_all_kernel<<<24576, 256>>>((const float4*)x, (const float4*)w1,
                                     (const float4*)w2);
    {
        dim3 grid(H_DIM / 128, M_TOK / 128);
        gemm_bf16_kernel<0><<<grid, 160, GEMM_SMEM>>>(xb, w1b, b1, hbuf,
                                                      D_DIM, H_DIM, 0, 1);
    }
    {
        size_t n4 = ((size_t)M_TOK * H_DIM) / 4;
        quant_h_kernel<<<(unsigned)(n4 / 256), 256>>>((const float4*)hbuf,
                                                      (ushort4*)hb, (int)n4);
    }
    {
        dim3 grid(D_DIM / 128, M_TOK / 128);
        gemm_bf16_kernel<1><<<grid, 160, GEMM_SMEM>>>(hb, w2b, b2, out,
                                                      H_DIM, D_DIM, 3, 2);
    }
    (void)in_sizes; (void)n_in; (void)out_size;
}